// round 8
// baseline (speedup 1.0000x reference)
#include <cuda_runtime.h>
#include <cuda_bf16.h>
#include <cstdint>

// ---------------------------------------------------------------------------
// GCNWithSubgraphs: gather-based, cp.async double-buffered tf32 MMA GEMMs
// writing bf16 h (dinv-prescaled), pure-sum bf16 gather with fp32 accum.
// out[c] = dinv_c * ( sum_{r in N(c)} hs[r] + hs[c] ),  hs[r] = (xW)[r]*dinv_r
// ---------------------------------------------------------------------------

#define H 256
#define H2 128   // bf16x2 words per row
#define MAX_NSUB  32768
#define MAX_NGLOB 65536
#define MAX_S     1024
#define MAX_ESUB  262144
#define MAX_EGLOB 1048576

__device__ uint32_t g_h_sub[MAX_NSUB * H2];    // bf16x2 hs_sub
__device__ uint32_t g_h_glob[MAX_NGLOB * H2];  // bf16x2 hs_glob (+ scaled inject)
__device__ uint32_t g_pooledW[MAX_S * H2];     // bf16x2 pool_mean @ W_glob
__device__ float g_pool_sum[MAX_S * H];
__device__ float g_pool_cnt[MAX_S];
__device__ float g_gemb[H];

__device__ int   g_cnt_sub[MAX_NSUB];
__device__ int   g_off_sub[MAX_NSUB + 1];
__device__ int   g_cur_sub[MAX_NSUB];
__device__ float g_dinv_sub[MAX_NSUB];
__device__ int   g_srcs_sub[MAX_ESUB];

__device__ int   g_cnt_glob[MAX_NGLOB];
__device__ int   g_off_glob[MAX_NGLOB + 1];
__device__ int   g_cur_glob[MAX_NGLOB];
__device__ float g_dinv_glob[MAX_NGLOB];
__device__ int   g_srcs_glob[MAX_EGLOB];

__device__ int   g_bsum_sub[256];
__device__ int   g_bsum_glob[256];

__device__ __forceinline__ void red_add_v4(float* a, float v0, float v1, float v2, float v3) {
    asm volatile("red.global.add.v4.f32 [%0], {%1,%2,%3,%4};"
                 :: "l"(a), "f"(v0), "f"(v1), "f"(v2), "f"(v3)
                 : "memory");
}

__device__ __forceinline__ void cp_async16(void* smem_dst, const void* gmem_src) {
    uint32_t s = (uint32_t)__cvta_generic_to_shared(smem_dst);
    asm volatile("cp.async.cg.shared.global [%0], [%1], 16;" :: "r"(s), "l"(gmem_src));
}
__device__ __forceinline__ void cp_commit() {
    asm volatile("cp.async.commit_group;" ::: "memory");
}
template <int N>
__device__ __forceinline__ void cp_wait() {
    asm volatile("cp.async.wait_group %0;" :: "n"(N) : "memory");
}

// ---------------------------------------------------------------------------
// 1) init
__global__ void k_init(int n_sub, int n_glob, int s) {
    int i = blockIdx.x * blockDim.x + threadIdx.x;
    if (i < n_sub)  g_cnt_sub[i]  = 0;
    if (i < n_glob) g_cnt_glob[i] = 0;
    if (i < s * H)  g_pool_sum[i] = 0.0f;
    if (i < s)      g_pool_cnt[i] = 0.0f;
    if (i < H)      g_gemb[i]     = 0.0f;
}

// 2) counts
__global__ void k_count_all(const int* __restrict__ cols_sub, int E_sub,
                            const int* __restrict__ cols_glob, int E_glob,
                            const int* __restrict__ batch, int n_sub) {
    int i = blockIdx.x * blockDim.x + threadIdx.x;
    if (i < E_glob) atomicAdd(&g_cnt_glob[cols_glob[i]], 1);
    if (i < E_sub)  atomicAdd(&g_cnt_sub[cols_sub[i]], 1);
    if (i < n_sub)  atomicAdd(&g_pool_cnt[batch[i]], 1.0f);
}

// 3) dinv
__global__ void k_dinv(int n_sub, int n_glob) {
    int i = blockIdx.x * blockDim.x + threadIdx.x;
    if (i < n_sub)  g_dinv_sub[i]  = rsqrtf((float)(g_cnt_sub[i] + 1));
    if (i < n_glob) g_dinv_glob[i] = rsqrtf((float)(g_cnt_glob[i] + 1));
}

// ---------------------------------------------------------------------------
// tf32 MMA GEMM: C[M,256](bf16x2) = (A[M,256] @ B[256,256]) * rowscale.
// cp.async double-buffered; A smem [m][36], B smem [k][136]; no STS, no cvt.
// Block 128x128, 256 threads, 8 warps (4x2), warp tile 32x64, m16n8k8, BK=32.
// ---------------------------------------------------------------------------
#define ASP 36
#define BSP 136
#define ASZ (128 * ASP)
#define BSZ (32 * BSP)
#define STG (ASZ + BSZ)
#define MMA_SMEM (2 * STG * 4)

__global__ __launch_bounds__(256) void k_mma(const float* __restrict__ A,
                                             const float* __restrict__ B,
                                             uint32_t* __restrict__ C,
                                             const float* __restrict__ rowscale, int M) {
    extern __shared__ float sm[];

    const int tid  = threadIdx.x;
    const int lane = tid & 31;
    const int wid  = tid >> 5;
    const int warpM = wid >> 1;
    const int warpN = wid & 1;
    const int g  = lane >> 2;
    const int tg = lane & 3;
    const int mb = warpM * 32;
    const int nb = warpN * 64;

    const int bc = blockIdx.x;
    const int br = blockIdx.y;

    const float* Ab = A + (size_t)br * 128 * H;
    const float* Bb = B + bc * 128;

    float c[2][8][4];
    #pragma unroll
    for (int mt = 0; mt < 2; mt++)
        #pragma unroll
        for (int nt = 0; nt < 8; nt++)
            #pragma unroll
            for (int i = 0; i < 4; i++) c[mt][nt][i] = 0.0f;

    auto load_tiles = [&](int stage, int k0) {
        float* as = sm + stage * STG;
        float* bs = as + ASZ;
        #pragma unroll
        for (int p = 0; p < 4; p++) {
            int idx = tid + p * 256;
            int row = idx >> 3;
            int c4  = (idx & 7) * 4;
            cp_async16(&as[row * ASP + c4], Ab + (size_t)row * H + k0 + c4);
        }
        #pragma unroll
        for (int p = 0; p < 4; p++) {
            int idx = tid + p * 256;
            int row = idx >> 5;
            int c4  = (idx & 31) * 4;
            cp_async16(&bs[row * BSP + c4], Bb + (size_t)(k0 + row) * H + c4);
        }
        cp_commit();
    };

    load_tiles(0, 0);

    const int NIT = H / 32;
    for (int it = 0; it < NIT; it++) {
        if (it + 1 < NIT) {
            load_tiles((it + 1) & 1, (it + 1) * 32);
            cp_wait<1>();
        } else {
            cp_wait<0>();
        }
        __syncthreads();

        const uint32_t* as = (const uint32_t*)(sm + (it & 1) * STG);
        const uint32_t* bs = as + ASZ;

        #pragma unroll
        for (int kk = 0; kk < 4; kk++) {
            const int k = kk * 8;
            uint32_t a[2][4];
            #pragma unroll
            for (int mt = 0; mt < 2; mt++) {
                int m = mb + mt * 16 + g;
                a[mt][0] = as[(size_t)m * ASP + k + tg];
                a[mt][1] = as[(size_t)(m + 8) * ASP + k + tg];
                a[mt][2] = as[(size_t)m * ASP + k + tg + 4];
                a[mt][3] = as[(size_t)(m + 8) * ASP + k + tg + 4];
            }
            #pragma unroll
            for (int nt = 0; nt < 8; nt++) {
                int n = nb + nt * 8 + g;
                uint32_t b0 = bs[(size_t)(k + tg) * BSP + n];
                uint32_t b1 = bs[(size_t)(k + tg + 4) * BSP + n];
                #pragma unroll
                for (int mt = 0; mt < 2; mt++) {
                    asm volatile(
                        "mma.sync.aligned.m16n8k8.row.col.f32.tf32.tf32.f32 "
                        "{%0,%1,%2,%3}, {%4,%5,%6,%7}, {%8,%9}, {%0,%1,%2,%3};"
                        : "+f"(c[mt][nt][0]), "+f"(c[mt][nt][1]),
                          "+f"(c[mt][nt][2]), "+f"(c[mt][nt][3])
                        : "r"(a[mt][0]), "r"(a[mt][1]), "r"(a[mt][2]), "r"(a[mt][3]),
                          "r"(b0), "r"(b1));
                }
            }
        }
        __syncthreads();
    }

    // writeback bf16x2 (rowscale applied in fp32 before rounding)
    uint32_t* Cb = C + (size_t)br * 128 * H2 + bc * 64;
    #pragma unroll
    for (int mt = 0; mt < 2; mt++) {
        int r0 = mb + mt * 16 + g;
        float s0 = 1.0f, s1 = 1.0f;
        if (rowscale) {
            s0 = __ldg(&rowscale[br * 128 + r0]);
            s1 = __ldg(&rowscale[br * 128 + r0 + 8]);
        }
        #pragma unroll
        for (int nt = 0; nt < 8; nt++) {
            int col2 = (nb + nt * 8 + 2 * tg) >> 1;
            __nv_bfloat162 lo = __float22bfloat162_rn(make_float2(c[mt][nt][0] * s0, c[mt][nt][1] * s0));
            __nv_bfloat162 hi = __float22bfloat162_rn(make_float2(c[mt][nt][2] * s1, c[mt][nt][3] * s1));
            Cb[(size_t)r0 * H2 + col2]       = *(uint32_t*)&lo;
            Cb[(size_t)(r0 + 8) * H2 + col2] = *(uint32_t*)&hi;
        }
    }
}

// ---------------------------------------------------------------------------
// counting sort (both graphs batched)
// ---------------------------------------------------------------------------
__global__ void k_blocksum_all(int NB_sub) {
    __shared__ int sh[256];
    int t = threadIdx.x;
    bool is_sub = (blockIdx.x < NB_sub);
    const int* cnt = is_sub ? g_cnt_sub : g_cnt_glob;
    int cb = is_sub ? blockIdx.x : blockIdx.x - NB_sub;
    sh[t] = cnt[cb * 256 + t];
    __syncthreads();
    #pragma unroll
    for (int s = 128; s > 0; s >>= 1) {
        if (t < s) sh[t] += sh[t + s];
        __syncthreads();
    }
    if (t == 0) (is_sub ? g_bsum_sub : g_bsum_glob)[cb] = sh[0];
}

__global__ void k_scan_bsum_all(int NB_sub, int NB_glob) {
    __shared__ int sh[256];
    int t = threadIdx.x;
    int* bsum = (blockIdx.x == 0) ? g_bsum_sub : g_bsum_glob;
    int NB = (blockIdx.x == 0) ? NB_sub : NB_glob;
    sh[t] = (t < NB) ? bsum[t] : 0;
    __syncthreads();
    #pragma unroll
    for (int d = 1; d < 256; d <<= 1) {
        int v = (t >= d) ? sh[t - d] : 0;
        __syncthreads();
        sh[t] += v;
        __syncthreads();
    }
    int ex = (t == 0) ? 0 : sh[t - 1];
    if (t < NB) bsum[t] = ex;
}

__global__ void k_scan_chunks_all(int NB_sub, int n_sub, int n_glob) {
    __shared__ int sh[256];
    int t = threadIdx.x;
    bool is_sub = (blockIdx.x < NB_sub);
    const int* cnt = is_sub ? g_cnt_sub : g_cnt_glob;
    const int* bsum = is_sub ? g_bsum_sub : g_bsum_glob;
    int* off = is_sub ? g_off_sub : g_off_glob;
    int* cur = is_sub ? g_cur_sub : g_cur_glob;
    int N = is_sub ? n_sub : n_glob;
    int cb = is_sub ? blockIdx.x : blockIdx.x - NB_sub;
    int i = cb * 256 + t;
    int c = cnt[i];
    sh[t] = c;
    __syncthreads();
    #pragma unroll
    for (int d = 1; d < 256; d <<= 1) {
        int v = (t >= d) ? sh[t - d] : 0;
        __syncthreads();
        sh[t] += v;
        __syncthreads();
    }
    int excl = sh[t] - c + bsum[cb];
    off[i] = excl;
    cur[i] = excl;
    if (i == N - 1) off[N] = excl + c;
}

__global__ void k_bucket_all(const int* __restrict__ rows_sub,
                             const int* __restrict__ cols_sub, int E_sub,
                             const int* __restrict__ rows_glob,
                             const int* __restrict__ cols_glob, int E_glob) {
    int i = blockIdx.x * blockDim.x + threadIdx.x;
    if (i < E_sub) {
        int c = cols_sub[i];
        int p = atomicAdd(&g_cur_sub[c], 1);
        g_srcs_sub[p] = rows_sub[i];
    }
    int e = i - E_sub;
    if (e >= 0 && e < E_glob) {
        int c = cols_glob[e];
        int p = atomicAdd(&g_cur_glob[c], 1);
        g_srcs_glob[p] = rows_glob[e];
    }
}

// ---------------------------------------------------------------------------
// gather core: warp per node; lane owns 8 channels [8*lane..8*lane+7].
// bf16 rows (32 uint4/row), fp32 accumulators, pure-sum, 4-edge batched.
// ---------------------------------------------------------------------------
__device__ __forceinline__ void bf8_init(uint4 v, float* acc) {
    const __nv_bfloat162* p = reinterpret_cast<const __nv_bfloat162*>(&v);
    #pragma unroll
    for (int i = 0; i < 4; i++) {
        float2 f = __bfloat1622float2(p[i]);
        acc[2 * i]     = f.x;
        acc[2 * i + 1] = f.y;
    }
}
__device__ __forceinline__ void bf8_add(uint4 v, float* acc) {
    const __nv_bfloat162* p = reinterpret_cast<const __nv_bfloat162*>(&v);
    #pragma unroll
    for (int i = 0; i < 4; i++) {
        float2 f = __bfloat1622float2(p[i]);
        acc[2 * i]     += f.x;
        acc[2 * i + 1] += f.y;
    }
}

__device__ __forceinline__ void gather_node(const uint4* __restrict__ hp,
                                            const int* __restrict__ off,
                                            const int* __restrict__ srcs,
                                            int n, int lane, float* acc) {
    int base = off[n];
    int end  = off[n + 1];

    bf8_init(__ldg(hp + (size_t)n * 32 + lane), acc);

    int e = base;
    for (; e + 4 <= end; e += 4) {
        int r0 = __ldg(&srcs[e + 0]);
        int r1 = __ldg(&srcs[e + 1]);
        int r2 = __ldg(&srcs[e + 2]);
        int r3 = __ldg(&srcs[e + 3]);
        uint4 v0 = __ldg(hp + (size_t)r0 * 32 + lane);
        uint4 v1 = __ldg(hp + (size_t)r1 * 32 + lane);
        uint4 v2 = __ldg(hp + (size_t)r2 * 32 + lane);
        uint4 v3 = __ldg(hp + (size_t)r3 * 32 + lane);
        bf8_add(v0, acc);
        bf8_add(v1, acc);
        bf8_add(v2, acc);
        bf8_add(v3, acc);
    }
    for (; e < end; e++) {
        int r = __ldg(&srcs[e]);
        bf8_add(__ldg(hp + (size_t)r * 32 + lane), acc);
    }
}

// sub: *dinv_c, +bias, relu, *1/cnt, pool red
__global__ __launch_bounds__(256) void k_gather_sub(const uint4* __restrict__ h,
                                                    const float* __restrict__ bias,
                                                    const int* __restrict__ batch, int N) {
    int warp = (blockIdx.x * blockDim.x + threadIdx.x) >> 5;
    int lane = threadIdx.x & 31;
    if (warp >= N) return;
    float acc[8];
    gather_node(h, g_off_sub, g_srcs_sub, warp, lane, acc);
    float di = g_dinv_sub[warp];
    int s = batch[warp];
    float ic = 1.0f / fmaxf(g_pool_cnt[s], 1.0f);
    const float* bp = bias + 8 * lane;
    #pragma unroll
    for (int i = 0; i < 8; i++)
        acc[i] = fmaxf(acc[i] * di + __ldg(bp + i), 0.0f) * ic;
    float* ps = g_pool_sum + (size_t)s * H + 8 * lane;
    red_add_v4(ps,     acc[0], acc[1], acc[2], acc[3]);
    red_add_v4(ps + 4, acc[4], acc[5], acc[6], acc[7]);
}

// glob: *dinv_c, +bias, relu, shared reduce -> gemb atomics
__global__ __launch_bounds__(512) void k_gather_glob(const uint4* __restrict__ h,
                                                     const float* __restrict__ bias, int N) {
    __shared__ float sh[H];
    int t = threadIdx.x;
    if (t < H) sh[t] = 0.0f;
    __syncthreads();

    int warp = (blockIdx.x * blockDim.x + t) >> 5;
    int lane = t & 31;
    if (warp < N) {
        float acc[8];
        gather_node(h, g_off_glob, g_srcs_glob, warp, lane, acc);
        float di = g_dinv_glob[warp];
        const float* bp = bias + 8 * lane;
        float* shp = sh + 8 * lane;
        #pragma unroll
        for (int i = 0; i < 8; i++) {
            float v = fmaxf(acc[i] * di + __ldg(bp + i), 0.0f);
            atomicAdd(shp + i, v);
        }
    }
    __syncthreads();
    if (t < H) atomicAdd(&g_gemb[t], sh[t]);
}

// hs_glob[sub_index[g]] += pooledW[g] * dinv_glob[node]   (bf16x2 atomics)
__global__ void k_inject(const int* __restrict__ sub_index, int s) {
    int i = blockIdx.x * blockDim.x + threadIdx.x;     // bf16x2 index
    if (i < s * H2) {
        int g = i >> 7;
        int j = i & (H2 - 1);
        int node = sub_index[g];
        float di = g_dinv_glob[node];
        __nv_bfloat162 v = *reinterpret_cast<const __nv_bfloat162*>(&g_pooledW[i]);
        float2 f = __bfloat1622float2(v);
        f.x *= di; f.y *= di;
        __nv_bfloat162 sv = __float22bfloat162_rn(f);
        atomicAdd(reinterpret_cast<__nv_bfloat162*>(&g_h_glob[(size_t)node * H2 + j]), sv);
    }
}

// out[j] = (gemb/n_glob) . fc_W[j,:] + fc_b[j]
__global__ void k_final(const float* __restrict__ fc_W, const float* __restrict__ fc_b,
                        float* __restrict__ out, float inv_n) {
    __shared__ float ge[H];
    int t = threadIdx.x;
    ge[t] = g_gemb[t] * inv_n;
    __syncthreads();
    float s = 0.0f;
    #pragma unroll 8
    for (int f = 0; f < H; f++) s += ge[f] * fc_W[t * H + f];
    out[t] = s + fc_b[t];
}

// ---------------------------------------------------------------------------
extern "C" void kernel_launch(void* const* d_in, const int* in_sizes, int n_in,
                              void* d_out, int out_size) {
    const float* x_sub      = (const float*)d_in[0];
    const int*   ei_sub     = (const int*)  d_in[1];
    const int*   batch_sub  = (const int*)  d_in[2];
    const int*   sub_index  = (const int*)  d_in[3];
    const float* x_glob     = (const float*)d_in[4];
    const int*   ei_glob    = (const int*)  d_in[5];
    const float* W_sub      = (const float*)d_in[7];
    const float* b_sub      = (const float*)d_in[8];
    const float* W_glob     = (const float*)d_in[9];
    const float* b_glob     = (const float*)d_in[10];
    const float* fc_W       = (const float*)d_in[11];
    const float* fc_b       = (const float*)d_in[12];
    float* out = (float*)d_out;

    const int n_sub  = in_sizes[0] / H;
    const int E_sub  = in_sizes[1] / 2;
    const int S      = in_sizes[3];
    const int n_glob = in_sizes[4] / H;
    const int E_glob = in_sizes[5] / 2;

    const int* rows_sub  = ei_sub;
    const int* cols_sub  = ei_sub + E_sub;
    const int* rows_glob = ei_glob;
    const int* cols_glob = ei_glob + E_glob;

    uint32_t* h_sub  ; cudaGetSymbolAddress((void**)&h_sub,   g_h_sub);
    uint32_t* h_glob ; cudaGetSymbolAddress((void**)&h_glob,  g_h_glob);
    uint32_t* pooledW; cudaGetSymbolAddress((void**)&pooledW, g_pooledW);
    float* psum      ; cudaGetSymbolAddress((void**)&psum,    g_pool_sum);
    float* dinv_sub  ; cudaGetSymbolAddress((void**)&dinv_sub,  g_dinv_sub);
    float* dinv_glob ; cudaGetSymbolAddress((void**)&dinv_glob, g_dinv_glob);

    cudaFuncSetAttribute(k_mma, cudaFuncAttributeMaxDynamicSharedMemorySize, MMA_SMEM);

    const int T = 256;
    const int NB_sub  = n_sub  / 256;
    const int NB_glob = n_glob / 256;

    // 1) init
    {
        int span = S * H;
        if (n_glob > span) span = n_glob;
        k_init<<<(span + T - 1) / T, T>>>(n_sub, n_glob, S);
    }
    // 2) counts
    k_count_all<<<(E_glob + T - 1) / T, T>>>(cols_sub, E_sub, cols_glob, E_glob,
                                             batch_sub, n_sub);
    // 3) dinv
    k_dinv<<<(n_glob + T - 1) / T, T>>>(n_sub, n_glob);

    // 4) BIG GEMM (profiled slot): hs_glob = (x_glob @ W_glob) * dinv_glob -> bf16
    k_mma<<<dim3(2, n_glob / 128), 256, MMA_SMEM>>>(x_glob, W_glob, h_glob, dinv_glob, n_glob);
    // 5) hs_sub
    k_mma<<<dim3(2, n_sub / 128), 256, MMA_SMEM>>>(x_sub, W_sub, h_sub, dinv_sub, n_sub);

    // 6-9) counting sort
    k_blocksum_all<<<NB_sub + NB_glob, 256>>>(NB_sub);
    k_scan_bsum_all<<<2, 256>>>(NB_sub, NB_glob);
    k_scan_chunks_all<<<NB_sub + NB_glob, 256>>>(NB_sub, n_sub, n_glob);
    k_bucket_all<<<(E_sub + E_glob + T - 1) / T, T>>>(rows_sub, cols_sub, E_sub,
                                                      rows_glob, cols_glob, E_glob);

    // 10) sub gather
    k_gather_sub<<<(n_sub * 32 + 255) / 256, 256>>>((const uint4*)h_sub, b_sub,
                                                    batch_sub, n_sub);
    // 11) pooledW = pool_mean @ W_glob -> bf16
    k_mma<<<dim3(2, S / 128), 256, MMA_SMEM>>>(psum, W_glob, pooledW, (const float*)nullptr, S);
    // 12) inject
    k_inject<<<(S * H2 + T - 1) / T, T>>>(sub_index, S);

    // 13) glob gather
    k_gather_glob<<<(n_glob * 32 + 511) / 512, 512>>>((const uint4*)h_glob, b_glob, n_glob);

    // 14) FC
    k_final<<<1, H>>>(fc_W, fc_b, out, 1.0f / (float)n_glob);
}

// round 9
// speedup vs baseline: 1.0328x; 1.0328x over previous
#include <cuda_runtime.h>
#include <cuda_bf16.h>
#include <cstdint>

// ---------------------------------------------------------------------------
// GCNWithSubgraphs: gather-based, cp.async tf32 MMA GEMMs (dinv-prescaled
// fp32 output), pure-sum gathers, stream-forked capture graph:
//   {mma_glob} || {sort} || {mma_sub -> gather_sub -> mma_pool}  then
//   inject -> gather_glob(channel-split) -> final.
// ---------------------------------------------------------------------------

#define H 256
#define MAX_NSUB  32768
#define MAX_NGLOB 65536
#define MAX_S     1024
#define MAX_ESUB  262144
#define MAX_EGLOB 1048576

__device__ float g_h_sub[MAX_NSUB * H];
__device__ float g_h_glob[MAX_NGLOB * H];
__device__ float g_pooledW[MAX_S * H];
__device__ float g_pool_sum[MAX_S * H];
__device__ float g_pool_cnt[MAX_S];
__device__ float g_gemb[H];

__device__ int   g_cnt_sub[MAX_NSUB];
__device__ int   g_off_sub[MAX_NSUB + 1];
__device__ int   g_cur_sub[MAX_NSUB];
__device__ float g_dinv_sub[MAX_NSUB];
__device__ int   g_srcs_sub[MAX_ESUB];

__device__ int   g_cnt_glob[MAX_NGLOB];
__device__ int   g_off_glob[MAX_NGLOB + 1];
__device__ int   g_cur_glob[MAX_NGLOB];
__device__ float g_dinv_glob[MAX_NGLOB];
__device__ int   g_srcs_glob[MAX_EGLOB];

__device__ int   g_bsum_sub[256];
__device__ int   g_bsum_glob[256];

__device__ __forceinline__ void red_add_v4(float* a, float v0, float v1, float v2, float v3) {
    asm volatile("red.global.add.v4.f32 [%0], {%1,%2,%3,%4};"
                 :: "l"(a), "f"(v0), "f"(v1), "f"(v2), "f"(v3)
                 : "memory");
}

__device__ __forceinline__ void cp_async16(void* smem_dst, const void* gmem_src) {
    uint32_t s = (uint32_t)__cvta_generic_to_shared(smem_dst);
    asm volatile("cp.async.cg.shared.global [%0], [%1], 16;" :: "r"(s), "l"(gmem_src));
}
__device__ __forceinline__ void cp_commit() {
    asm volatile("cp.async.commit_group;" ::: "memory");
}
template <int N>
__device__ __forceinline__ void cp_wait() {
    asm volatile("cp.async.wait_group %0;" :: "n"(N) : "memory");
}

// ---------------------------------------------------------------------------
__global__ void k_init(int n_sub, int n_glob, int s) {
    int i = blockIdx.x * blockDim.x + threadIdx.x;
    if (i < n_sub)  g_cnt_sub[i]  = 0;
    if (i < n_glob) g_cnt_glob[i] = 0;
    if (i < s * H)  g_pool_sum[i] = 0.0f;
    if (i < s)      g_pool_cnt[i] = 0.0f;
    if (i < H)      g_gemb[i]     = 0.0f;
}

__global__ void k_count_all(const int* __restrict__ cols_sub, int E_sub,
                            const int* __restrict__ cols_glob, int E_glob,
                            const int* __restrict__ batch, int n_sub) {
    int i = blockIdx.x * blockDim.x + threadIdx.x;
    if (i < E_glob) atomicAdd(&g_cnt_glob[cols_glob[i]], 1);
    if (i < E_sub)  atomicAdd(&g_cnt_sub[cols_sub[i]], 1);
    if (i < n_sub)  atomicAdd(&g_pool_cnt[batch[i]], 1.0f);
}

__global__ void k_dinv(int n_sub, int n_glob) {
    int i = blockIdx.x * blockDim.x + threadIdx.x;
    if (i < n_sub)  g_dinv_sub[i]  = rsqrtf((float)(g_cnt_sub[i] + 1));
    if (i < n_glob) g_dinv_glob[i] = rsqrtf((float)(g_cnt_glob[i] + 1));
}

// ---------------------------------------------------------------------------
// tf32 MMA GEMM: C[M,256](f32) = (A[M,256] @ B[256,256]) * rowscale
// cp.async double-buffered, no STS, no cvt. 128x128 block, 256 thr, BK=32.
// ---------------------------------------------------------------------------
#define ASP 36
#define BSP 136
#define ASZ (128 * ASP)
#define BSZ (32 * BSP)
#define STG (ASZ + BSZ)
#define MMA_SMEM (2 * STG * 4)

__global__ __launch_bounds__(256) void k_mma(const float* __restrict__ A,
                                             const float* __restrict__ B,
                                             float* __restrict__ C,
                                             const float* __restrict__ rowscale, int M) {
    extern __shared__ float sm[];

    const int tid  = threadIdx.x;
    const int lane = tid & 31;
    const int wid  = tid >> 5;
    const int warpM = wid >> 1;
    const int warpN = wid & 1;
    const int g  = lane >> 2;
    const int tg = lane & 3;
    const int mb = warpM * 32;
    const int nb = warpN * 64;

    const int bc = blockIdx.x;
    const int br = blockIdx.y;

    const float* Ab = A + (size_t)br * 128 * H;
    const float* Bb = B + bc * 128;

    float c[2][8][4];
    #pragma unroll
    for (int mt = 0; mt < 2; mt++)
        #pragma unroll
        for (int nt = 0; nt < 8; nt++)
            #pragma unroll
            for (int i = 0; i < 4; i++) c[mt][nt][i] = 0.0f;

    auto load_tiles = [&](int stage, int k0) {
        float* as = sm + stage * STG;
        float* bs = as + ASZ;
        #pragma unroll
        for (int p = 0; p < 4; p++) {
            int idx = tid + p * 256;
            int row = idx >> 3;
            int c4  = (idx & 7) * 4;
            cp_async16(&as[row * ASP + c4], Ab + (size_t)row * H + k0 + c4);
        }
        #pragma unroll
        for (int p = 0; p < 4; p++) {
            int idx = tid + p * 256;
            int row = idx >> 5;
            int c4  = (idx & 31) * 4;
            cp_async16(&bs[row * BSP + c4], Bb + (size_t)(k0 + row) * H + c4);
        }
        cp_commit();
    };

    load_tiles(0, 0);

    const int NIT = H / 32;
    for (int it = 0; it < NIT; it++) {
        if (it + 1 < NIT) {
            load_tiles((it + 1) & 1, (it + 1) * 32);
            cp_wait<1>();
        } else {
            cp_wait<0>();
        }
        __syncthreads();

        const uint32_t* as = (const uint32_t*)(sm + (it & 1) * STG);
        const uint32_t* bs = as + ASZ;

        #pragma unroll
        for (int kk = 0; kk < 4; kk++) {
            const int k = kk * 8;
            uint32_t a[2][4];
            #pragma unroll
            for (int mt = 0; mt < 2; mt++) {
                int m = mb + mt * 16 + g;
                a[mt][0] = as[(size_t)m * ASP + k + tg];
                a[mt][1] = as[(size_t)(m + 8) * ASP + k + tg];
                a[mt][2] = as[(size_t)m * ASP + k + tg + 4];
                a[mt][3] = as[(size_t)(m + 8) * ASP + k + tg + 4];
            }
            #pragma unroll
            for (int nt = 0; nt < 8; nt++) {
                int n = nb + nt * 8 + g;
                uint32_t b0 = bs[(size_t)(k + tg) * BSP + n];
                uint32_t b1 = bs[(size_t)(k + tg + 4) * BSP + n];
                #pragma unroll
                for (int mt = 0; mt < 2; mt++) {
                    asm volatile(
                        "mma.sync.aligned.m16n8k8.row.col.f32.tf32.tf32.f32 "
                        "{%0,%1,%2,%3}, {%4,%5,%6,%7}, {%8,%9}, {%0,%1,%2,%3};"
                        : "+f"(c[mt][nt][0]), "+f"(c[mt][nt][1]),
                          "+f"(c[mt][nt][2]), "+f"(c[mt][nt][3])
                        : "r"(a[mt][0]), "r"(a[mt][1]), "r"(a[mt][2]), "r"(a[mt][3]),
                          "r"(b0), "r"(b1));
                }
            }
        }
        __syncthreads();
    }

    float* Cb = C + (size_t)br * 128 * H + bc * 128;
    #pragma unroll
    for (int mt = 0; mt < 2; mt++) {
        int r0 = mb + mt * 16 + g;
        float s0 = 1.0f, s1 = 1.0f;
        if (rowscale) {
            s0 = __ldg(&rowscale[br * 128 + r0]);
            s1 = __ldg(&rowscale[br * 128 + r0 + 8]);
        }
        #pragma unroll
        for (int nt = 0; nt < 8; nt++) {
            int col = nb + nt * 8 + 2 * tg;
            *(float2*)(Cb + (size_t)r0 * H + col)       = make_float2(c[mt][nt][0] * s0, c[mt][nt][1] * s0);
            *(float2*)(Cb + (size_t)(r0 + 8) * H + col) = make_float2(c[mt][nt][2] * s1, c[mt][nt][3] * s1);
        }
    }
}

// ---------------------------------------------------------------------------
// counting sort (both graphs batched)
// ---------------------------------------------------------------------------
__global__ void k_blocksum_all(int NB_sub) {
    __shared__ int sh[256];
    int t = threadIdx.x;
    bool is_sub = (blockIdx.x < NB_sub);
    const int* cnt = is_sub ? g_cnt_sub : g_cnt_glob;
    int cb = is_sub ? blockIdx.x : blockIdx.x - NB_sub;
    sh[t] = cnt[cb * 256 + t];
    __syncthreads();
    #pragma unroll
    for (int s = 128; s > 0; s >>= 1) {
        if (t < s) sh[t] += sh[t + s];
        __syncthreads();
    }
    if (t == 0) (is_sub ? g_bsum_sub : g_bsum_glob)[cb] = sh[0];
}

__global__ void k_scan_bsum_all(int NB_sub, int NB_glob) {
    __shared__ int sh[256];
    int t = threadIdx.x;
    int* bsum = (blockIdx.x == 0) ? g_bsum_sub : g_bsum_glob;
    int NB = (blockIdx.x == 0) ? NB_sub : NB_glob;
    sh[t] = (t < NB) ? bsum[t] : 0;
    __syncthreads();
    #pragma unroll
    for (int d = 1; d < 256; d <<= 1) {
        int v = (t >= d) ? sh[t - d] : 0;
        __syncthreads();
        sh[t] += v;
        __syncthreads();
    }
    int ex = (t == 0) ? 0 : sh[t - 1];
    if (t < NB) bsum[t] = ex;
}

__global__ void k_scan_chunks_all(int NB_sub, int n_sub, int n_glob) {
    __shared__ int sh[256];
    int t = threadIdx.x;
    bool is_sub = (blockIdx.x < NB_sub);
    const int* cnt = is_sub ? g_cnt_sub : g_cnt_glob;
    const int* bsum = is_sub ? g_bsum_sub : g_bsum_glob;
    int* off = is_sub ? g_off_sub : g_off_glob;
    int* cur = is_sub ? g_cur_sub : g_cur_glob;
    int N = is_sub ? n_sub : n_glob;
    int cb = is_sub ? blockIdx.x : blockIdx.x - NB_sub;
    int i = cb * 256 + t;
    int c = cnt[i];
    sh[t] = c;
    __syncthreads();
    #pragma unroll
    for (int d = 1; d < 256; d <<= 1) {
        int v = (t >= d) ? sh[t - d] : 0;
        __syncthreads();
        sh[t] += v;
        __syncthreads();
    }
    int excl = sh[t] - c + bsum[cb];
    off[i] = excl;
    cur[i] = excl;
    if (i == N - 1) off[N] = excl + c;
}

__global__ void k_bucket_all(const int* __restrict__ rows_sub,
                             const int* __restrict__ cols_sub, int E_sub,
                             const int* __restrict__ rows_glob,
                             const int* __restrict__ cols_glob, int E_glob) {
    int i = blockIdx.x * blockDim.x + threadIdx.x;
    if (i < E_sub) {
        int c = cols_sub[i];
        int p = atomicAdd(&g_cur_sub[c], 1);
        g_srcs_sub[p] = rows_sub[i];
    }
    int e = i - E_sub;
    if (e >= 0 && e < E_glob) {
        int c = cols_glob[e];
        int p = atomicAdd(&g_cur_glob[c], 1);
        g_srcs_glob[p] = rows_glob[e];
    }
}

// ---------------------------------------------------------------------------
// sub gather: warp per node; lane owns float4 {lane, lane+32}; 4-edge batch.
// ---------------------------------------------------------------------------
__device__ __forceinline__ void f4_add2(float4 v0, float4 v1, float* acc) {
    acc[0] += v0.x; acc[1] += v0.y; acc[2] += v0.z; acc[3] += v0.w;
    acc[4] += v1.x; acc[5] += v1.y; acc[6] += v1.z; acc[7] += v1.w;
}

__global__ __launch_bounds__(256) void k_gather_sub(const float4* __restrict__ h,
                                                    const float* __restrict__ bias,
                                                    const int* __restrict__ batch, int N) {
    int warp = (blockIdx.x * blockDim.x + threadIdx.x) >> 5;
    int lane = threadIdx.x & 31;
    if (warp >= N) return;

    int base = g_off_sub[warp];
    int end  = g_off_sub[warp + 1];
    const int* srcs = g_srcs_sub;

    float acc[8];
    {
        float4 s0 = __ldg(h + (size_t)warp * 64 + lane);
        float4 s1 = __ldg(h + (size_t)warp * 64 + lane + 32);
        acc[0] = s0.x; acc[1] = s0.y; acc[2] = s0.z; acc[3] = s0.w;
        acc[4] = s1.x; acc[5] = s1.y; acc[6] = s1.z; acc[7] = s1.w;
    }
    int e = base;
    for (; e + 4 <= end; e += 4) {
        int r0 = __ldg(&srcs[e + 0]);
        int r1 = __ldg(&srcs[e + 1]);
        int r2 = __ldg(&srcs[e + 2]);
        int r3 = __ldg(&srcs[e + 3]);
        float4 a0 = __ldg(h + (size_t)r0 * 64 + lane);
        float4 b0 = __ldg(h + (size_t)r0 * 64 + lane + 32);
        float4 a1 = __ldg(h + (size_t)r1 * 64 + lane);
        float4 b1 = __ldg(h + (size_t)r1 * 64 + lane + 32);
        float4 a2 = __ldg(h + (size_t)r2 * 64 + lane);
        float4 b2 = __ldg(h + (size_t)r2 * 64 + lane + 32);
        float4 a3 = __ldg(h + (size_t)r3 * 64 + lane);
        float4 b3 = __ldg(h + (size_t)r3 * 64 + lane + 32);
        f4_add2(a0, b0, acc);
        f4_add2(a1, b1, acc);
        f4_add2(a2, b2, acc);
        f4_add2(a3, b3, acc);
    }
    for (; e < end; e++) {
        int r = __ldg(&srcs[e]);
        float4 a = __ldg(h + (size_t)r * 64 + lane);
        float4 b = __ldg(h + (size_t)r * 64 + lane + 32);
        f4_add2(a, b, acc);
    }

    float di = g_dinv_sub[warp];
    int s = batch[warp];
    float ic = 1.0f / fmaxf(g_pool_cnt[s], 1.0f);
    const float* bp = bias + 4 * lane;
    #pragma unroll
    for (int i = 0; i < 4; i++)
        acc[i] = fmaxf(acc[i] * di + __ldg(bp + i), 0.0f) * ic;
    #pragma unroll
    for (int i = 0; i < 4; i++)
        acc[4 + i] = fmaxf(acc[4 + i] * di + __ldg(bp + 128 + i), 0.0f) * ic;
    float* ps = g_pool_sum + (size_t)s * H;
    red_add_v4(ps + 4 * lane,       acc[0], acc[1], acc[2], acc[3]);
    red_add_v4(ps + 128 + 4 * lane, acc[4], acc[5], acc[6], acc[7]);
}

// ---------------------------------------------------------------------------
// glob gather: warp per (node, channel-half); 1 float4/lane/edge; 8-edge batch.
// ---------------------------------------------------------------------------
__global__ __launch_bounds__(512) void k_gather_glob(const float4* __restrict__ h,
                                                     const float* __restrict__ bias, int N) {
    __shared__ float sh[H];
    int t = threadIdx.x;
    if (t < H) sh[t] = 0.0f;
    __syncthreads();

    int gwarp = (blockIdx.x * blockDim.x + t) >> 5;
    int lane = t & 31;
    int node = gwarp >> 1;
    int half = gwarp & 1;
    if (node < N) {
        int base = g_off_glob[node];
        int end  = g_off_glob[node + 1];
        const int* srcs = g_srcs_glob;
        int fo = half * 32 + lane;            // float4 offset within row

        float4 acc = __ldg(h + (size_t)node * 64 + fo);

        int e = base;
        for (; e + 8 <= end; e += 8) {
            int r0 = __ldg(&srcs[e + 0]);
            int r1 = __ldg(&srcs[e + 1]);
            int r2 = __ldg(&srcs[e + 2]);
            int r3 = __ldg(&srcs[e + 3]);
            int r4 = __ldg(&srcs[e + 4]);
            int r5 = __ldg(&srcs[e + 5]);
            int r6 = __ldg(&srcs[e + 6]);
            int r7 = __ldg(&srcs[e + 7]);
            float4 v0 = __ldg(h + (size_t)r0 * 64 + fo);
            float4 v1 = __ldg(h + (size_t)r1 * 64 + fo);
            float4 v2 = __ldg(h + (size_t)r2 * 64 + fo);
            float4 v3 = __ldg(h + (size_t)r3 * 64 + fo);
            float4 v4 = __ldg(h + (size_t)r4 * 64 + fo);
            float4 v5 = __ldg(h + (size_t)r5 * 64 + fo);
            float4 v6 = __ldg(h + (size_t)r6 * 64 + fo);
            float4 v7 = __ldg(h + (size_t)r7 * 64 + fo);
            acc.x += v0.x + v1.x + v2.x + v3.x + v4.x + v5.x + v6.x + v7.x;
            acc.y += v0.y + v1.y + v2.y + v3.y + v4.y + v5.y + v6.y + v7.y;
            acc.z += v0.z + v1.z + v2.z + v3.z + v4.z + v5.z + v6.z + v7.z;
            acc.w += v0.w + v1.w + v2.w + v3.w + v4.w + v5.w + v6.w + v7.w;
        }
        for (; e < end; e++) {
            int r = __ldg(&srcs[e]);
            float4 v = __ldg(h + (size_t)r * 64 + fo);
            acc.x += v.x; acc.y += v.y; acc.z += v.z; acc.w += v.w;
        }

        float di = g_dinv_glob[node];
        int ch = 4 * fo;                      // channel base
        const float* bp = bias + ch;
        float o0 = fmaxf(acc.x * di + __ldg(bp + 0), 0.0f);
        float o1 = fmaxf(acc.y * di + __ldg(bp + 1), 0.0f);
        float o2 = fmaxf(acc.z * di + __ldg(bp + 2), 0.0f);
        float o3 = fmaxf(acc.w * di + __ldg(bp + 3), 0.0f);
        atomicAdd(&sh[ch + 0], o0);
        atomicAdd(&sh[ch + 1], o1);
        atomicAdd(&sh[ch + 2], o2);
        atomicAdd(&sh[ch + 3], o3);
    }
    __syncthreads();
    if (t < H) atomicAdd(&g_gemb[t], sh[t]);
}

// hs_glob[sub_index[g]] += pooledW[g] * dinv_glob[node]
__global__ void k_inject(const int* __restrict__ sub_index, int s) {
    int i = blockIdx.x * blockDim.x + threadIdx.x;
    if (i < s * 64) {
        int g  = i >> 6;
        int f4 = i & 63;
        int node = sub_index[g];
        float di = g_dinv_glob[node];
        float4 v = ((const float4*)g_pooledW)[i];
        red_add_v4(&g_h_glob[(size_t)node * H + 4 * f4],
                   v.x * di, v.y * di, v.z * di, v.w * di);
    }
}

__global__ void k_final(const float* __restrict__ fc_W, const float* __restrict__ fc_b,
                        float* __restrict__ out, float inv_n) {
    __shared__ float ge[H];
    int t = threadIdx.x;
    ge[t] = g_gemb[t] * inv_n;
    __syncthreads();
    float s = 0.0f;
    #pragma unroll 8
    for (int f = 0; f < H; f++) s += ge[f] * fc_W[t * H + f];
    out[t] = s + fc_b[t];
}

// ---------------------------------------------------------------------------
extern "C" void kernel_launch(void* const* d_in, const int* in_sizes, int n_in,
                              void* d_out, int out_size) {
    const float* x_sub      = (const float*)d_in[0];
    const int*   ei_sub     = (const int*)  d_in[1];
    const int*   batch_sub  = (const int*)  d_in[2];
    const int*   sub_index  = (const int*)  d_in[3];
    const float* x_glob     = (const float*)d_in[4];
    const int*   ei_glob    = (const int*)  d_in[5];
    const float* W_sub      = (const float*)d_in[7];
    const float* b_sub      = (const float*)d_in[8];
    const float* W_glob     = (const float*)d_in[9];
    const float* b_glob     = (const float*)d_in[10];
    const float* fc_W       = (const float*)d_in[11];
    const float* fc_b       = (const float*)d_in[12];
    float* out = (float*)d_out;

    const int n_sub  = in_sizes[0] / H;
    const int E_sub  = in_sizes[1] / 2;
    const int S      = in_sizes[3];
    const int n_glob = in_sizes[4] / H;
    const int E_glob = in_sizes[5] / 2;

    const int* rows_sub  = ei_sub;
    const int* cols_sub  = ei_sub + E_sub;
    const int* rows_glob = ei_glob;
    const int* cols_glob = ei_glob + E_glob;

    float* h_sub   ; cudaGetSymbolAddress((void**)&h_sub,    g_h_sub);
    float* h_glob  ; cudaGetSymbolAddress((void**)&h_glob,   g_h_glob);
    float* pooledW ; cudaGetSymbolAddress((void**)&pooledW,  g_pooledW);
    float* psum    ; cudaGetSymbolAddress((void**)&psum,     g_pool_sum);
    float* dinv_sub ; cudaGetSymbolAddress((void**)&dinv_sub,  g_dinv_sub);
    float* dinv_glob; cudaGetSymbolAddress((void**)&dinv_glob, g_dinv_glob);

    cudaFuncSetAttribute(k_mma, cudaFuncAttributeMaxDynamicSharedMemorySize, MMA_SMEM);

    // one-time host-side objects (no device memory; identical work per call)
    static cudaStream_t s_sort = nullptr, s_glob = nullptr;
    static cudaEvent_t evRoot = nullptr, evSort = nullptr, evGlobM = nullptr;
    if (!s_sort) {
        cudaStreamCreateWithFlags(&s_sort, cudaStreamNonBlocking);
        cudaStreamCreateWithFlags(&s_glob, cudaStreamNonBlocking);
        cudaEventCreateWithFlags(&evRoot,  cudaEventDisableTiming);
        cudaEventCreateWithFlags(&evSort,  cudaEventDisableTiming);
        cudaEventCreateWithFlags(&evGlobM, cudaEventDisableTiming);
    }

    const int T = 256;
    const int NB_sub  = n_sub  / 256;
    const int NB_glob = n_glob / 256;

    // ---- serial prologue on capture stream ----
    {
        int span = S * H;
        if (n_glob > span) span = n_glob;
        k_init<<<(span + T - 1) / T, T>>>(n_sub, n_glob, S);
    }
    k_count_all<<<(E_glob + T - 1) / T, T>>>(cols_sub, E_sub, cols_glob, E_glob,
                                             batch_sub, n_sub);
    k_dinv<<<(n_glob + T - 1) / T, T>>>(n_sub, n_glob);
    cudaEventRecord(evRoot, 0);

    // ---- branch A (s_sort): counting sort ----
    cudaStreamWaitEvent(s_sort, evRoot, 0);
    k_blocksum_all<<<NB_sub + NB_glob, 256, 0, s_sort>>>(NB_sub);
    k_scan_bsum_all<<<2, 256, 0, s_sort>>>(NB_sub, NB_glob);
    k_scan_chunks_all<<<NB_sub + NB_glob, 256, 0, s_sort>>>(NB_sub, n_sub, n_glob);
    k_bucket_all<<<(E_sub + E_glob + T - 1) / T, T, 0, s_sort>>>(rows_sub, cols_sub, E_sub,
                                                                 rows_glob, cols_glob, E_glob);
    cudaEventRecord(evSort, s_sort);

    // ---- branch B (s_glob): big glob GEMM ----
    cudaStreamWaitEvent(s_glob, evRoot, 0);
    k_mma<<<dim3(2, n_glob / 128), 256, MMA_SMEM, s_glob>>>(x_glob, W_glob, h_glob,
                                                            dinv_glob, n_glob);
    cudaEventRecord(evGlobM, s_glob);

    // ---- main stream: sub pipeline ----
    k_mma<<<dim3(2, n_sub / 128), 256, MMA_SMEM>>>(x_sub, W_sub, h_sub, dinv_sub, n_sub);
    cudaStreamWaitEvent(0, evSort, 0);
    k_gather_sub<<<(n_sub * 32 + 255) / 256, 256>>>((const float4*)h_sub, b_sub,
                                                    batch_sub, n_sub);
    k_mma<<<dim3(2, S / 128), 256, MMA_SMEM>>>(psum, W_glob, pooledW,
                                               (const float*)nullptr, S);
    // ---- join + epilogue ----
    cudaStreamWaitEvent(0, evGlobM, 0);
    k_inject<<<(S * 64 + T - 1) / T, T>>>(sub_index, S);
    k_gather_glob<<<(n_glob * 64 + 511) / 512, 512>>>((const float4*)h_glob, b_glob, n_glob);
    k_final<<<1, H>>>(fc_W, fc_b, out, 1.0f / (float)n_glob);
}